// round 2
// baseline (speedup 1.0000x reference)
#include <cuda_runtime.h>

#define NB    65536
#define DIM   256
#define HID   64
#define ACT   18
#define NEXP  8
#define ROWS  128
#define NTHR  256
#define HSTR  132   // activation smem row stride (col-major [k][row]), padded
#define W6STR 20    // W6 smem row stride (>=18, float4-friendly)

#define SMEM_FLOATS (2 * HID * HSTR + HID * HID + HID * W6STR)
#define SMEM_BYTES  (SMEM_FLOATS * 4)

typedef unsigned long long u64;

// ---------------- scratch (no allocations allowed) ----------------
__device__ int g_counts[NEXP];
__device__ int g_offsets[NEXP + 1];
__device__ int g_cursor[NEXP];
__device__ int g_perm[NB];

// ---------------- sort rows by expert ----------------
__global__ void k_zero() {
    if (threadIdx.x < NEXP) g_counts[threadIdx.x] = 0;
}

__global__ void k_hist(const int* __restrict__ rm) {
    __shared__ int s_cnt[NEXP];
    int t = threadIdx.x;
    if (t < NEXP) s_cnt[t] = 0;
    __syncthreads();
    int i = blockIdx.x * NTHR + t;
    atomicAdd(&s_cnt[rm[i]], 1);
    __syncthreads();
    if (t < NEXP) atomicAdd(&g_counts[t], s_cnt[t]);
}

__global__ void k_prefix() {
    int off = 0;
    for (int e = 0; e < NEXP; e++) {
        g_offsets[e] = off;
        g_cursor[e]  = off;
        off += g_counts[e];
    }
    g_offsets[NEXP] = off;
}

__global__ void k_scatter(const int* __restrict__ rm) {
    __shared__ int s_cnt[NEXP], s_base[NEXP];
    int t = threadIdx.x;
    if (t < NEXP) s_cnt[t] = 0;
    __syncthreads();
    int i = blockIdx.x * NTHR + t;
    int e = rm[i];
    int loc = atomicAdd(&s_cnt[e], 1);
    __syncthreads();
    if (t < NEXP) s_base[t] = atomicAdd(&g_cursor[t], s_cnt[t]);
    __syncthreads();
    g_perm[s_base[e] + loc] = i;
}

// ---------------- packed f32x2 helpers ----------------
__device__ __forceinline__ u64 splat2(float w) {
    u64 r;
    asm("mov.b64 %0, {%1, %1};" : "=l"(r) : "f"(w));
    return r;
}
__device__ __forceinline__ void fma2(u64& acc, u64 h, u64 w) {
    asm("fma.rn.f32x2 %0, %1, %2, %0;" : "+l"(acc) : "l"(h), "l"(w));
}
__device__ __forceinline__ void unpack2(u64 v, float& lo, float& hi) {
    asm("mov.b64 {%0, %1}, %2;" : "=f"(lo), "=f"(hi) : "l"(v));
}

// ---------------- fused per-expert MLP ----------------
// grid: (tiles=NB/ROWS, NEXP). Block handles 128 rows of one expert.
// Thread tile: 8 rows x 4 cols; acc packed as 4 row-pairs x 4 cols (f32x2).
__global__ void __launch_bounds__(NTHR, 2) k_moe(
    const float* __restrict__ X,
    const float* __restrict__ W1, const float* __restrict__ b1,
    const float* __restrict__ W2, const float* __restrict__ b2,
    const float* __restrict__ W3, const float* __restrict__ b3,
    const float* __restrict__ W4, const float* __restrict__ b4,
    const float* __restrict__ W5, const float* __restrict__ b5,
    const float* __restrict__ W6, const float* __restrict__ b6,
    float* __restrict__ out)
{
    extern __shared__ float smem[];
    float* sH0 = smem;                      // [HID][HSTR] activations ping
    float* sH1 = smem + HID * HSTR;         // pong
    float* sW  = smem + 2 * HID * HSTR;     // [64][64] current weight
    float* sW6 = sW + HID * HID;            // [64][W6STR]

    const int e    = blockIdx.y;
    const int off  = g_offsets[e];
    const int cnt  = g_offsets[e + 1] - off;
    const int tile = blockIdx.x;
    if (tile * ROWS >= cnt) return;
    const int nrows = min(ROWS, cnt - tile * ROWS);

    const int tid = threadIdx.x;
    const int rg  = tid & 15;       // row group 0..15
    const int cg  = tid >> 4;       // col group 0..15
    const int rb  = rg * 8;
    const int cb  = cg * 4;

    // X staging mapping: thread covers half a row's 64-float chunk
    const int lr   = tid >> 1;
    const int half = tid & 1;
    const float* xrow = nullptr;
    if (lr < nrows) {
        int grow = g_perm[off + tile * ROWS + lr];
        xrow = X + (size_t)grow * DIM;
    }

    u64 acc[4][4];   // row-pairs (2p,2p+1) x cols
    #pragma unroll
    for (int p = 0; p < 4; p++)
        #pragma unroll
        for (int j = 0; j < 4; j++) acc[p][j] = 0ull;

    // ---------- Layer 1: [128,256] @ [256,64], 4 k-chunks of 64 ----------
    const float* W1e = W1 + (size_t)e * DIM * HID;
    for (int kc = 0; kc < 4; kc++) {
        // transpose-stage X chunk into sH0[k][row]
        #pragma unroll
        for (int v = 0; v < 8; v++) {
            float4 d = make_float4(0.f, 0.f, 0.f, 0.f);
            if (xrow) d = *(const float4*)(xrow + kc * 64 + half * 32 + v * 4);
            int k0 = half * 32 + v * 4;
            sH0[(k0 + 0) * HSTR + lr] = d.x;
            sH0[(k0 + 1) * HSTR + lr] = d.y;
            sH0[(k0 + 2) * HSTR + lr] = d.z;
            sH0[(k0 + 3) * HSTR + lr] = d.w;
        }
        // stage W1 chunk (contiguous 64x64)
        const float4* wsrc = (const float4*)(W1e + kc * 64 * HID);
        #pragma unroll
        for (int v = 0; v < 4; v++)
            ((float4*)sW)[tid + v * NTHR] = wsrc[tid + v * NTHR];
        __syncthreads();

        #pragma unroll 16
        for (int k = 0; k < 64; k++) {
            float4 wv = *(const float4*)(sW + k * HID + cb);
            ulonglong2 ha = *(const ulonglong2*)(sH0 + k * HSTR + rb);
            ulonglong2 hb = *(const ulonglong2*)(sH0 + k * HSTR + rb + 4);
            u64 h2[4] = { ha.x, ha.y, hb.x, hb.y };
            u64 ws[4] = { splat2(wv.x), splat2(wv.y), splat2(wv.z), splat2(wv.w) };
            #pragma unroll
            for (int p = 0; p < 4; p++)
                #pragma unroll
                for (int j = 0; j < 4; j++)
                    fma2(acc[p][j], h2[p], ws[j]);
        }
        __syncthreads();
    }
    // bias + relu -> sH0 (col-major)
    {
        const float* be = b1 + e * HID;
        #pragma unroll
        for (int j = 0; j < 4; j++) {
            float bj = be[cb + j];
            float r[8];
            #pragma unroll
            for (int p = 0; p < 4; p++) {
                float lo, hi;
                unpack2(acc[p][j], lo, hi);
                r[2 * p]     = fmaxf(lo + bj, 0.f);
                r[2 * p + 1] = fmaxf(hi + bj, 0.f);
            }
            *(float4*)(sH0 + (cb + j) * HSTR + rb)     = make_float4(r[0], r[1], r[2], r[3]);
            *(float4*)(sH0 + (cb + j) * HSTR + rb + 4) = make_float4(r[4], r[5], r[6], r[7]);
        }
    }
    __syncthreads();

    // ---------- Layers 2..5: [128,64] @ [64,64], ping-pong ----------
    const float* Wls[4] = { W2 + (size_t)e * HID * HID, W3 + (size_t)e * HID * HID,
                            W4 + (size_t)e * HID * HID, W5 + (size_t)e * HID * HID };
    const float* bls[4] = { b2 + e * HID, b3 + e * HID, b4 + e * HID, b5 + e * HID };
    float* bufs[2] = { sH0, sH1 };

    #pragma unroll
    for (int l = 0; l < 4; l++) {
        float* sHc = bufs[l & 1];
        float* sHn = bufs[(l & 1) ^ 1];
        const float4* wsrc = (const float4*)(Wls[l]);
        #pragma unroll
        for (int v = 0; v < 4; v++)
            ((float4*)sW)[tid + v * NTHR] = wsrc[tid + v * NTHR];
        __syncthreads();

        #pragma unroll
        for (int p = 0; p < 4; p++)
            #pragma unroll
            for (int j = 0; j < 4; j++) acc[p][j] = 0ull;

        #pragma unroll 16
        for (int k = 0; k < 64; k++) {
            float4 wv = *(const float4*)(sW + k * HID + cb);
            ulonglong2 ha = *(const ulonglong2*)(sHc + k * HSTR + rb);
            ulonglong2 hb = *(const ulonglong2*)(sHc + k * HSTR + rb + 4);
            u64 h2[4] = { ha.x, ha.y, hb.x, hb.y };
            u64 ws[4] = { splat2(wv.x), splat2(wv.y), splat2(wv.z), splat2(wv.w) };
            #pragma unroll
            for (int p = 0; p < 4; p++)
                #pragma unroll
                for (int j = 0; j < 4; j++)
                    fma2(acc[p][j], h2[p], ws[j]);
        }
        const float* be = bls[l];
        #pragma unroll
        for (int j = 0; j < 4; j++) {
            float bj = be[cb + j];
            float r[8];
            #pragma unroll
            for (int p = 0; p < 4; p++) {
                float lo, hi;
                unpack2(acc[p][j], lo, hi);
                r[2 * p]     = fmaxf(lo + bj, 0.f);
                r[2 * p + 1] = fmaxf(hi + bj, 0.f);
            }
            *(float4*)(sHn + (cb + j) * HSTR + rb)     = make_float4(r[0], r[1], r[2], r[3]);
            *(float4*)(sHn + (cb + j) * HSTR + rb + 4) = make_float4(r[4], r[5], r[6], r[7]);
        }
        __syncthreads();
    }

    // ---------- Layer 6: [128,64] @ [64,18], no relu ----------
    float* sHf = bufs[0];  // after 4 layers final activations are back in sH0
    const float* W6e = W6 + (size_t)e * HID * ACT;
    for (int i2 = tid; i2 < HID * ACT; i2 += NTHR)
        sW6[(i2 / ACT) * W6STR + (i2 % ACT)] = W6e[i2];
    __syncthreads();

    int pr[8];
    #pragma unroll
    for (int i = 0; i < 8; i++) {
        int r = rb + i;
        pr[i] = (r < nrows) ? g_perm[off + tile * ROWS + r] : -1;
    }

    if (cb < ACT) {
        u64 accO[4][4];
        #pragma unroll
        for (int p = 0; p < 4; p++)
            #pragma unroll
            for (int j = 0; j < 4; j++) accO[p][j] = 0ull;

        #pragma unroll 16
        for (int k = 0; k < 64; k++) {
            ulonglong2 ha = *(const ulonglong2*)(sHf + k * HSTR + rb);
            ulonglong2 hb = *(const ulonglong2*)(sHf + k * HSTR + rb + 4);
            u64 h2[4] = { ha.x, ha.y, hb.x, hb.y };
            u64 ws[4];
            #pragma unroll
            for (int j = 0; j < 4; j++) ws[j] = splat2(sW6[k * W6STR + cb + j]);
            #pragma unroll
            for (int p = 0; p < 4; p++)
                #pragma unroll
                for (int j = 0; j < 4; j++)
                    fma2(accO[p][j], h2[p], ws[j]);
        }
        const float* b6e = b6 + e * ACT;
        #pragma unroll
        for (int j = 0; j < 4; j++) {
            int c = cb + j;
            if (c < ACT) {
                float bj = b6e[c];
                #pragma unroll
                for (int p = 0; p < 4; p++) {
                    float lo, hi;
                    unpack2(accO[p][j], lo, hi);
                    if (pr[2 * p]     >= 0) out[(size_t)pr[2 * p]     * ACT + c] = lo + bj;
                    if (pr[2 * p + 1] >= 0) out[(size_t)pr[2 * p + 1] * ACT + c] = hi + bj;
                }
            }
        }
    }
}

extern "C" void kernel_launch(void* const* d_in, const int* in_sizes, int n_in,
                              void* d_out, int out_size) {
    const float* X  = (const float*)d_in[0];
    const int*   rm = (const int*)d_in[1];
    const float* W1 = (const float*)d_in[2];  const float* b1 = (const float*)d_in[3];
    const float* W2 = (const float*)d_in[4];  const float* b2 = (const float*)d_in[5];
    const float* W3 = (const float*)d_in[6];  const float* b3 = (const float*)d_in[7];
    const float* W4 = (const float*)d_in[8];  const float* b4 = (const float*)d_in[9];
    const float* W5 = (const float*)d_in[10]; const float* b5 = (const float*)d_in[11];
    const float* W6 = (const float*)d_in[12]; const float* b6 = (const float*)d_in[13];
    float* out = (float*)d_out;

    cudaFuncSetAttribute(k_moe, cudaFuncAttributeMaxDynamicSharedMemorySize, SMEM_BYTES);

    k_zero<<<1, 32>>>();
    k_hist<<<NB / NTHR, NTHR>>>(rm);
    k_prefix<<<1, 1>>>();
    k_scatter<<<NB / NTHR, NTHR>>>(rm);

    dim3 grid(NB / ROWS, NEXP);
    k_moe<<<grid, NTHR, SMEM_BYTES>>>(X, W1, b1, W2, b2, W3, b3, W4, b4,
                                      W5, b5, W6, b6, out);
}

// round 4
// speedup vs baseline: 2.0149x; 2.0149x over previous
#include <cuda_runtime.h>
#include <cuda_bf16.h>
#include <cstdint>

#define NB    65536
#define DIM   256
#define HID   64
#define ACT   18
#define NEXP  8
#define ROWS  128
#define NTHR  256
#define HPAD  72        // halves per row (stride), 144B

// smem byte offsets
#define SH_HI 0
#define SH_LO 18432
#define SW_HI 36864
#define SW_LO 46080
#define SBIAS 55296
#define SMEM_TOTAL 55552

// ---------------- scratch ----------------
__device__ int g_counts[NEXP];
__device__ int g_offsets[NEXP + 1];
__device__ int g_cursor[NEXP];
__device__ int g_perm[NB];

// ---------------- sort ----------------
#define SORT_THR 256
__global__ void k_zero() { if (threadIdx.x < NEXP) g_counts[threadIdx.x] = 0; }

__global__ void k_hist(const int4* __restrict__ rm) {
    __shared__ int s_cnt[NEXP];
    int t = threadIdx.x;
    if (t < NEXP) s_cnt[t] = 0;
    __syncthreads();
    int4 v = rm[blockIdx.x * SORT_THR + t];
    atomicAdd(&s_cnt[v.x], 1); atomicAdd(&s_cnt[v.y], 1);
    atomicAdd(&s_cnt[v.z], 1); atomicAdd(&s_cnt[v.w], 1);
    __syncthreads();
    if (t < NEXP) atomicAdd(&g_counts[t], s_cnt[t]);
}

__global__ void k_prefix() {
    int off = 0;
    for (int e = 0; e < NEXP; e++) { g_offsets[e] = off; g_cursor[e] = off; off += g_counts[e]; }
    g_offsets[NEXP] = off;
}

__global__ void k_scatter(const int4* __restrict__ rm) {
    __shared__ int s_cnt[NEXP], s_base[NEXP];
    int t = threadIdx.x;
    if (t < NEXP) s_cnt[t] = 0;
    __syncthreads();
    int i = blockIdx.x * SORT_THR + t;
    int4 v = rm[i];
    int l0 = atomicAdd(&s_cnt[v.x], 1);
    int l1 = atomicAdd(&s_cnt[v.y], 1);
    int l2 = atomicAdd(&s_cnt[v.z], 1);
    int l3 = atomicAdd(&s_cnt[v.w], 1);
    __syncthreads();
    if (t < NEXP) s_base[t] = atomicAdd(&g_cursor[t], s_cnt[t]);
    __syncthreads();
    int b = i * 4;
    g_perm[s_base[v.x] + l0] = b;
    g_perm[s_base[v.y] + l1] = b + 1;
    g_perm[s_base[v.z] + l2] = b + 2;
    g_perm[s_base[v.w] + l3] = b + 3;
}

// ---------------- helpers ----------------
__device__ __forceinline__ uint32_t smem_u32(const void* p) {
    uint32_t a;
    asm("{ .reg .u64 t; cvta.to.shared.u64 t, %1; cvt.u32.u64 %0, t; }" : "=r"(a) : "l"(p));
    return a;
}
// pack: result halves = {lo16 = bf16(a), hi16 = bf16(b)}
__device__ __forceinline__ uint32_t bf2(float a, float b) {
    uint32_t r;
    asm("cvt.rn.bf16x2.f32 %0, %1, %2;" : "=r"(r) : "f"(b), "f"(a));
    return r;
}
__device__ __forceinline__ float bfr(float x) {   // residual after bf16 round
    __nv_bfloat16 h = __float2bfloat16(x);
    return x - __bfloat162float(h);
}

#define LDSM4(d, addr) \
    asm volatile("ldmatrix.sync.aligned.m8n8.x4.shared.b16 {%0,%1,%2,%3}, [%4];" \
        : "=r"((d)[0]), "=r"((d)[1]), "=r"((d)[2]), "=r"((d)[3]) : "r"(addr))

#define MMA(c, a, b0, b1) \
    asm volatile("mma.sync.aligned.m16n8k16.row.col.f32.bf16.bf16.f32 " \
        "{%0,%1,%2,%3},{%4,%5,%6,%7},{%8,%9},{%0,%1,%2,%3};" \
        : "+f"((c)[0]), "+f"((c)[1]), "+f"((c)[2]), "+f"((c)[3]) \
        : "r"((a)[0]), "r"((a)[1]), "r"((a)[2]), "r"((a)[3]), "r"(b0), "r"(b1))

// ---------------- fused MoE (mma.sync bf16 3-term split) ----------------
__global__ void __launch_bounds__(NTHR, 2) k_moe(
    const float* __restrict__ X,
    const float* __restrict__ W1, const float* __restrict__ b1,
    const float* __restrict__ W2, const float* __restrict__ b2,
    const float* __restrict__ W3, const float* __restrict__ b3,
    const float* __restrict__ W4, const float* __restrict__ b4,
    const float* __restrict__ W5, const float* __restrict__ b5,
    const float* __restrict__ W6, const float* __restrict__ b6,
    float* __restrict__ out)
{
    extern __shared__ char smem[];
    const int tid = threadIdx.x, wid = tid >> 5, lane = tid & 31;
    const int e = blockIdx.y, tile = blockIdx.x;
    const int off = g_offsets[e];
    const int cnt = g_offsets[e + 1] - off;
    if (tile * ROWS >= cnt) return;
    const int nrows = min(ROWS, cnt - tile * ROWS);

    const uint32_t sb  = smem_u32(smem);
    const uint32_t shi = sb + SH_HI, slo = sb + SH_LO;
    const uint32_t whi = sb + SW_HI, wlo = sb + SW_LO;
    float* sBias = (float*)(smem + SBIAS);

    const int rbase = wid * 16;

    // ldmatrix lane-address components (bytes, plane-relative)
    const uint32_t aRow = (uint32_t)(rbase + (lane & 7) + ((lane >> 3) & 1) * 8);
    const uint32_t aKof = ((lane >> 4) & 1) * 8;
    const uint32_t bRowL = (uint32_t)((lane & 7) + ((lane >> 4) & 1) * 8);
    const uint32_t bKof = ((lane >> 3) & 1) * 8;

    // X staging: 2 threads per row
    const int srow = tid >> 1, half = tid & 1;
    const int srowc = min(srow, nrows - 1);
    const float* xrow = X + (size_t)g_perm[off + tile * ROWS + srowc] * DIM + half * 32;

    float acc[8][4];
    #pragma unroll
    for (int i = 0; i < 8; i++)
        #pragma unroll
        for (int j = 0; j < 4; j++) acc[i][j] = 0.f;

    // ================= Layer 1: K=256 in 4 chunks of 64 =================
    const float* W1e = W1 + (size_t)e * DIM * HID;
    for (int c = 0; c < 4; c++) {
        if (c > 0) __syncthreads();
        // stage H chunk (32 floats per thread -> hi/lo planes)
        #pragma unroll
        for (int v = 0; v < 8; v++) {
            float4 d = *(const float4*)(xrow + c * 64 + v * 4);
            int k0 = half * 32 + v * 4;
            uint32_t o = (uint32_t)(srow * HPAD + k0) * 2;
            uint2 hp = make_uint2(bf2(d.x, d.y), bf2(d.z, d.w));
            uint2 lp = make_uint2(bf2(bfr(d.x), bfr(d.y)), bf2(bfr(d.z), bfr(d.w)));
            *(uint2*)(smem + SH_HI + o) = hp;
            *(uint2*)(smem + SH_LO + o) = lp;
        }
        // stage W chunk transposed: gmem [64k][64n] -> planes [n][k]
        {
            const float* Wc = W1e + (size_t)c * 64 * HID;
            #pragma unroll
            for (int it = 0; it < 16; it++) {
                int idx = tid + it * NTHR;
                int k = idx >> 6, n = idx & 63;
                float w = Wc[idx];
                uint32_t o = (uint32_t)(n * HPAD + k) * 2;
                *(__nv_bfloat16*)(smem + SW_HI + o) = __float2bfloat16(w);
                *(__nv_bfloat16*)(smem + SW_LO + o) = __float2bfloat16(bfr(w));
            }
        }
        __syncthreads();
        // mma over this K=64 chunk
        #pragma unroll
        for (int ks = 0; ks < 4; ks++) {
            uint32_t k0 = ks * 16;
            uint32_t aoff = (aRow * HPAD + k0 + aKof) * 2;
            uint32_t ahi[4], alo[4];
            LDSM4(ahi, shi + aoff);
            LDSM4(alo, slo + aoff);
            #pragma unroll
            for (int p = 0; p < 4; p++) {
                uint32_t boff = ((p * 16 + bRowL) * HPAD + k0 + bKof) * 2;
                uint32_t bh[4], bl[4];
                LDSM4(bh, whi + boff);
                LDSM4(bl, wlo + boff);
                MMA(acc[2 * p],     ahi, bh[0], bh[1]);
                MMA(acc[2 * p],     ahi, bl[0], bl[1]);
                MMA(acc[2 * p],     alo, bh[0], bh[1]);
                MMA(acc[2 * p + 1], ahi, bh[2], bh[3]);
                MMA(acc[2 * p + 1], ahi, bl[2], bl[3]);
                MMA(acc[2 * p + 1], alo, bh[2], bh[3]);
            }
        }
    }
    if (tid < HID) sBias[tid] = b1[e * HID + tid];
    __syncthreads();   // also covers last chunk reads before H overwrite below

    // ================= layers: epilogue then next GEMM =================
    const float* Wls[4] = { W2 + (size_t)e * HID * HID, W3 + (size_t)e * HID * HID,
                            W4 + (size_t)e * HID * HID, W5 + (size_t)e * HID * HID };
    const float* bls[4] = { b2 + e * HID, b3 + e * HID, b4 + e * HID, b5 + e * HID };

    const int erow = rbase + (lane >> 2);

    for (int l = 0; l <= 4; l++) {
        // ---- epilogue: bias + relu + split -> H planes (own rows only) ----
        #pragma unroll
        for (int nt = 0; nt < 8; nt++) {
            int c0 = nt * 8 + (lane & 3) * 2;
            float b0v = sBias[c0], b1v = sBias[c0 + 1];
            float v0 = fmaxf(acc[nt][0] + b0v, 0.f);
            float v1 = fmaxf(acc[nt][1] + b1v, 0.f);
            float v2 = fmaxf(acc[nt][2] + b0v, 0.f);
            float v3 = fmaxf(acc[nt][3] + b1v, 0.f);
            uint32_t o0 = (uint32_t)(erow * HPAD + c0) * 2;
            uint32_t o1 = (uint32_t)((erow + 8) * HPAD + c0) * 2;
            *(uint32_t*)(smem + SH_HI + o0) = bf2(v0, v1);
            *(uint32_t*)(smem + SH_HI + o1) = bf2(v2, v3);
            *(uint32_t*)(smem + SH_LO + o0) = bf2(bfr(v0), bfr(v1));
            *(uint32_t*)(smem + SH_LO + o1) = bf2(bfr(v2), bfr(v3));
        }
        __syncwarp();
        if (l == 4) break;

        __syncthreads();   // all warps done reading old W
        // stage W(l+2) transposed + bias
        {
            const float* Wc = Wls[l];
            #pragma unroll
            for (int it = 0; it < 16; it++) {
                int idx = tid + it * NTHR;
                int k = idx >> 6, n = idx & 63;
                float w = Wc[idx];
                uint32_t o = (uint32_t)(n * HPAD + k) * 2;
                *(__nv_bfloat16*)(smem + SW_HI + o) = __float2bfloat16(w);
                *(__nv_bfloat16*)(smem + SW_LO + o) = __float2bfloat16(bfr(w));
            }
            if (tid < HID) sBias[tid] = bls[l][tid];
        }
        __syncthreads();

        #pragma unroll
        for (int i = 0; i < 8; i++)
            #pragma unroll
            for (int j = 0; j < 4; j++) acc[i][j] = 0.f;

        #pragma unroll
        for (int ks = 0; ks < 4; ks++) {
            uint32_t k0 = ks * 16;
            uint32_t aoff = (aRow * HPAD + k0 + aKof) * 2;
            uint32_t ahi[4], alo[4];
            LDSM4(ahi, shi + aoff);
            LDSM4(alo, slo + aoff);
            #pragma unroll
            for (int p = 0; p < 4; p++) {
                uint32_t boff = ((p * 16 + bRowL) * HPAD + k0 + bKof) * 2;
                uint32_t bh[4], bl[4];
                LDSM4(bh, whi + boff);
                LDSM4(bl, wlo + boff);
                MMA(acc[2 * p],     ahi, bh[0], bh[1]);
                MMA(acc[2 * p],     ahi, bl[0], bl[1]);
                MMA(acc[2 * p],     alo, bh[0], bh[1]);
                MMA(acc[2 * p + 1], ahi, bh[2], bh[3]);
                MMA(acc[2 * p + 1], ahi, bl[2], bl[3]);
                MMA(acc[2 * p + 1], alo, bh[2], bh[3]);
            }
        }
    }

    // ================= Layer 6: [128,64]x[64,18] =================
    __syncthreads();   // done reading W5
    // zero first 32 n-rows of both W planes, then fill 18 cols
    {
        for (int idx = tid; idx < 32 * HPAD * 2 / 4; idx += NTHR) {
            *(uint32_t*)(smem + SW_HI + idx * 4) = 0u;
            *(uint32_t*)(smem + SW_LO + idx * 4) = 0u;
        }
        if (tid < 32) sBias[tid] = (tid < ACT) ? b6[e * ACT + tid] : 0.f;
    }
    __syncthreads();
    {
        const float* W6e = W6 + (size_t)e * HID * ACT;
        for (int idx = tid; idx < HID * ACT; idx += NTHR) {
            int k = idx / ACT, n = idx % ACT;
            float w = W6e[idx];
            uint32_t o = (uint32_t)(n * HPAD + k) * 2;
            *(__nv_bfloat16*)(smem + SW_HI + o) = __float2bfloat16(w);
            *(__nv_bfloat16*)(smem + SW_LO + o) = __float2bfloat16(bfr(w));
        }
    }
    __syncthreads();

    float acc6[3][4];
    #pragma unroll
    for (int i = 0; i < 3; i++)
        #pragma unroll
        for (int j = 0; j < 4; j++) acc6[i][j] = 0.f;

    #pragma unroll
    for (int ks = 0; ks < 4; ks++) {
        uint32_t k0 = ks * 16;
        uint32_t aoff = (aRow * HPAD + k0 + aKof) * 2;
        uint32_t ahi[4], alo[4];
        LDSM4(ahi, shi + aoff);
        LDSM4(alo, slo + aoff);
        #pragma unroll
        for (int p = 0; p < 2; p++) {
            uint32_t boff = ((p * 16 + bRowL) * HPAD + k0 + bKof) * 2;
            uint32_t bh[4], bl[4];
            LDSM4(bh, whi + boff);
            LDSM4(bl, wlo + boff);
            MMA(acc6[2 * p],     ahi, bh[0], bh[1]);
            MMA(acc6[2 * p],     ahi, bl[0], bl[1]);
            MMA(acc6[2 * p],     alo, bh[0], bh[1]);
            if (p == 0) {
                MMA(acc6[1], ahi, bh[2], bh[3]);
                MMA(acc6[1], ahi, bl[2], bl[3]);
                MMA(acc6[1], alo, bh[2], bh[3]);
            }
        }
    }

    // output scatter
    const int r0 = erow, r1 = erow + 8;
    int pr0 = (r0 < nrows) ? g_perm[off + tile * ROWS + r0] : -1;
    int pr1 = (r1 < nrows) ? g_perm[off + tile * ROWS + r1] : -1;
    #pragma unroll
    for (int nt = 0; nt < 3; nt++) {
        int c0 = nt * 8 + (lane & 3) * 2;
        if (c0 + 1 < ACT) {
            float b0v = sBias[c0], b1v = sBias[c0 + 1];
            if (pr0 >= 0) {
                out[(size_t)pr0 * ACT + c0]     = acc6[nt][0] + b0v;
                out[(size_t)pr0 * ACT + c0 + 1] = acc6[nt][1] + b1v;
            }
            if (pr1 >= 0) {
                out[(size_t)pr1 * ACT + c0]     = acc6[nt][2] + b0v;
                out[(size_t)pr1 * ACT + c0 + 1] = acc6[nt][3] + b1v;
            }
        }
    }
}

extern "C" void kernel_launch(void* const* d_in, const int* in_sizes, int n_in,
                              void* d_out, int out_size) {
    const float* X  = (const float*)d_in[0];
    const int*   rm = (const int*)d_in[1];
    const float* W1 = (const float*)d_in[2];  const float* b1 = (const float*)d_in[3];
    const float* W2 = (const float*)d_in[4];  const float* b2 = (const float*)d_in[5];
    const float* W3 = (const float*)d_in[6];  const float* b3 = (const float*)d_in[7];
    const float* W4 = (const float*)d_in[8];  const float* b4 = (const float*)d_in[9];
    const float* W5 = (const float*)d_in[10]; const float* b5 = (const float*)d_in[11];
    const float* W6 = (const float*)d_in[12]; const float* b6 = (const float*)d_in[13];
    float* out = (float*)d_out;

    cudaFuncSetAttribute(k_moe, cudaFuncAttributeMaxDynamicSharedMemorySize, SMEM_TOTAL);

    k_zero<<<1, 32>>>();
    k_hist<<<NB / (SORT_THR * 4), SORT_THR>>>((const int4*)rm);
    k_prefix<<<1, 1>>>();
    k_scatter<<<NB / (SORT_THR * 4), SORT_THR>>>((const int4*)rm);

    dim3 grid(NB / ROWS, NEXP);
    k_moe<<<grid, NTHR, SMEM_TOTAL>>>(X, W1, b1, W2, b2, W3, b3, W4, b4,
                                      W5, b5, W6, b6, out);
}

// round 5
// speedup vs baseline: 2.7714x; 1.3754x over previous
#include <cuda_runtime.h>
#include <cuda_bf16.h>
#include <cstdint>

#define NB    65536
#define DIM   256
#define HID   64
#define ACT   18
#define NEXP  8
#define ROWS  64
#define NTHR  128
#define HPAD  72        // halves per row stride (144B) -> conflict-free ldmatrix

// smem byte offsets
#define SH_HI 0
#define SH_LO 9216
#define SW_HI 18432
#define SW_LO 27648
#define SBIAS 36864     // 352 floats: b1..b5 (5*64) + b6 padded (32)
#define SMEM_TOTAL 38400

// ---------------- scratch ----------------
__device__ int g_counts[NEXP];
__device__ int g_offsets[NEXP + 1];
__device__ int g_cursor[NEXP];
__device__ int g_perm[NB];
// preconverted weights: per expert 9 slots (W1 c0..c3, W2..W5, W6) of 8192 bf16:
// hi plane [0,4096), lo plane [4096,8192); layout [n][64 k]
__device__ __align__(16) __nv_bfloat16 g_w[NEXP * 9 * 8192];

// ---------------- sort ----------------
#define SORT_THR 256
__global__ void k_zero() { if (threadIdx.x < NEXP) g_counts[threadIdx.x] = 0; }

__global__ void k_hist(const int4* __restrict__ rm) {
    __shared__ int s_cnt[NEXP];
    int t = threadIdx.x;
    if (t < NEXP) s_cnt[t] = 0;
    __syncthreads();
    int4 v = rm[blockIdx.x * SORT_THR + t];
    int vv[4] = { v.x, v.y, v.z, v.w };
    #pragma unroll
    for (int r = 0; r < 4; r++) {
        unsigned m = __match_any_sync(0xffffffffu, vv[r]);
        int leader = __ffs(m) - 1;
        if ((t & 31) == leader) atomicAdd(&s_cnt[vv[r]], __popc(m));
    }
    __syncthreads();
    if (t < NEXP) atomicAdd(&g_counts[t], s_cnt[t]);
}

__global__ void k_prefix() {
    int off = 0;
    for (int e = 0; e < NEXP; e++) { g_offsets[e] = off; g_cursor[e] = off; off += g_counts[e]; }
    g_offsets[NEXP] = off;
}

__global__ void k_scatter(const int4* __restrict__ rm) {
    __shared__ int s_cnt[NEXP], s_base[NEXP];
    int t = threadIdx.x;
    if (t < NEXP) s_cnt[t] = 0;
    __syncthreads();
    int i = blockIdx.x * SORT_THR + t;
    int4 v = rm[i];
    int vv[4] = { v.x, v.y, v.z, v.w };
    int loc[4];
    unsigned lt = (1u << (t & 31)) - 1u;
    #pragma unroll
    for (int r = 0; r < 4; r++) {
        unsigned m = __match_any_sync(0xffffffffu, vv[r]);
        int leader = __ffs(m) - 1;
        int base = 0;
        if ((t & 31) == leader) base = atomicAdd(&s_cnt[vv[r]], __popc(m));
        base = __shfl_sync(0xffffffffu, base, leader);
        loc[r] = base + __popc(m & lt);
    }
    __syncthreads();
    if (t < NEXP) s_base[t] = atomicAdd(&g_cursor[t], s_cnt[t]);
    __syncthreads();
    int b = i * 4;
    #pragma unroll
    for (int r = 0; r < 4; r++)
        g_perm[s_base[vv[r]] + loc[r]] = b + r;
}

// ---------------- weight preconvert ----------------
#define WCONV_TOTAL (NEXP * 34816)
__global__ void k_wconv(const float* __restrict__ W1, const float* __restrict__ W2,
                        const float* __restrict__ W3, const float* __restrict__ W4,
                        const float* __restrict__ W5, const float* __restrict__ W6) {
    int idx = blockIdx.x * blockDim.x + threadIdx.x;
    if (idx >= WCONV_TOTAL) return;
    int e = idx / 34816, r = idx % 34816;
    float w;
    int dst;
    if (r < 16384) {                   // W1 chunks 0..3
        int c = r >> 12, nk = r & 4095, n = nk >> 6, k = nk & 63;
        w = W1[((size_t)e * 256 + c * 64 + k) * 64 + n];
        dst = (e * 9 + c) * 8192 + nk;
    } else if (r < 32768) {            // W2..W5
        int l = (r - 16384) >> 12, nk = (r - 16384) & 4095, n = nk >> 6, k = nk & 63;
        const float* Wl = (l == 0) ? W2 : (l == 1) ? W3 : (l == 2) ? W4 : W5;
        w = Wl[((size_t)e * 64 + k) * 64 + n];
        dst = (e * 9 + 4 + l) * 8192 + nk;
    } else {                           // W6, n padded to 32
        int nk = r - 32768, n = nk >> 6, k = nk & 63;
        w = (n < ACT) ? W6[((size_t)e * 64 + k) * ACT + n] : 0.f;
        dst = (e * 9 + 8) * 8192 + nk;
    }
    __nv_bfloat16 h = __float2bfloat16(w);
    g_w[dst] = h;
    g_w[dst + 4096] = __float2bfloat16(w - __bfloat162float(h));
}

// ---------------- helpers ----------------
__device__ __forceinline__ uint32_t smem_u32(const void* p) {
    uint32_t a;
    asm("{ .reg .u64 t; cvta.to.shared.u64 t, %1; cvt.u32.u64 %0, t; }" : "=r"(a) : "l"(p));
    return a;
}
__device__ __forceinline__ uint32_t bf2(float a, float b) {
    uint32_t r;
    asm("cvt.rn.bf16x2.f32 %0, %1, %2;" : "=r"(r) : "f"(b), "f"(a));
    return r;
}
__device__ __forceinline__ float bfr(float x) {
    __nv_bfloat16 h = __float2bfloat16(x);
    return x - __bfloat162float(h);
}
#define CP16(dst, src) \
    asm volatile("cp.async.ca.shared.global [%0], [%1], 16;" :: "r"(dst), "l"(src))
#define CP_COMMIT() asm volatile("cp.async.commit_group;" ::: "memory")
#define CP_WAIT0()  asm volatile("cp.async.wait_group 0;" ::: "memory")

#define LDSM4(d, addr) \
    asm volatile("ldmatrix.sync.aligned.m8n8.x4.shared.b16 {%0,%1,%2,%3}, [%4];" \
        : "=r"((d)[0]), "=r"((d)[1]), "=r"((d)[2]), "=r"((d)[3]) : "r"(addr))

#define MMA(c, a, b0, b1) \
    asm volatile("mma.sync.aligned.m16n8k16.row.col.f32.bf16.bf16.f32 " \
        "{%0,%1,%2,%3},{%4,%5,%6,%7},{%8,%9},{%0,%1,%2,%3};" \
        : "+f"((c)[0]), "+f"((c)[1]), "+f"((c)[2]), "+f"((c)[3]) \
        : "r"((a)[0]), "r"((a)[1]), "r"((a)[2]), "r"((a)[3]), "r"(b0), "r"(b1))

// stage one weight slot (hi+lo planes) via cp.async; nW = rows (64 or 32)
__device__ __forceinline__ void stageW(uint32_t sw_hi, uint32_t sw_lo,
                                       const __nv_bfloat16* gw, int tid, int nW) {
    const char* src = (const char*)gw;
    int total = nW * 8;
    for (int i = tid; i < total; i += NTHR) {
        int n = i >> 3, j = i & 7;
        uint32_t d = n * (HPAD * 2) + j * 16;
        int s = (n * 64 + j * 8) * 2;
        CP16(sw_hi + d, src + s);
        CP16(sw_lo + d, src + 8192 + s);
    }
}

// ---------------- fused MoE ----------------
__global__ void __launch_bounds__(NTHR, 5) k_moe(
    const float* __restrict__ X,
    const float* __restrict__ b1, const float* __restrict__ b2,
    const float* __restrict__ b3, const float* __restrict__ b4,
    const float* __restrict__ b5, const float* __restrict__ b6,
    float* __restrict__ out)
{
    extern __shared__ char smem[];
    const int tid = threadIdx.x, wid = tid >> 5, lane = tid & 31;
    const int e = blockIdx.y, tile = blockIdx.x;
    const int off = g_offsets[e];
    const int cnt = g_offsets[e + 1] - off;
    if (tile * ROWS >= cnt) return;
    const int nrows = min(ROWS, cnt - tile * ROWS);

    const uint32_t sb  = smem_u32(smem);
    const uint32_t shi = sb + SH_HI, slo = sb + SH_LO;
    const uint32_t whi = sb + SW_HI, wlo = sb + SW_LO;
    float* sB = (float*)(smem + SBIAS);

    // bias preload (b1..b5 at l*64, b6 at 320)
    if (tid < 64) {
        sB[tid]       = b1[e * HID + tid];
        sB[64 + tid]  = b2[e * HID + tid];
        sB[128 + tid] = b3[e * HID + tid];
        sB[192 + tid] = b4[e * HID + tid];
        sB[256 + tid] = b5[e * HID + tid];
    }
    if (tid < 32) sB[320 + tid] = (tid < ACT) ? b6[e * ACT + tid] : 0.f;

    const __nv_bfloat16* gwE = g_w + (size_t)e * 9 * 8192;

    const int rbase = wid * 16;
    const uint32_t aRow  = (uint32_t)(rbase + (lane & 7) + ((lane >> 3) & 1) * 8);
    const uint32_t aKof  = ((lane >> 4) & 1) * 8;
    const uint32_t bRowL = (uint32_t)((lane & 7) + ((lane >> 4) & 1) * 8);
    const uint32_t bKof  = ((lane >> 3) & 1) * 8;

    // X staging: 2 threads per row; warp w stages exactly rows [16w,16w+16)
    const int srow = tid >> 1, half = tid & 1;
    const int srowc = min(srow, nrows - 1);
    const float* xrow = X + (size_t)g_perm[off + tile * ROWS + srowc] * DIM + half * 32;

    float acc[8][4];
    #pragma unroll
    for (int i = 0; i < 8; i++)
        #pragma unroll
        for (int j = 0; j < 4; j++) acc[i][j] = 0.f;

    // ================= Layer 1: K=256 in 4 chunks =================
    for (int c = 0; c < 4; c++) {
        if (c > 0) __syncthreads();        // prev MMA done reading W (and H)
        stageW(whi, wlo, gwE + c * 8192, tid, 64);
        #pragma unroll
        for (int v = 0; v < 8; v++) {
            float4 d = *(const float4*)(xrow + c * 64 + v * 4);
            int k0 = half * 32 + v * 4;
            uint32_t o = (uint32_t)(srow * HPAD + k0) * 2;
            *(uint2*)(smem + SH_HI + o) = make_uint2(bf2(d.x, d.y), bf2(d.z, d.w));
            *(uint2*)(smem + SH_LO + o) =
                make_uint2(bf2(bfr(d.x), bfr(d.y)), bf2(bfr(d.z), bfr(d.w)));
        }
        CP_COMMIT(); CP_WAIT0();
        __syncthreads();                   // W + H ready
        #pragma unroll
        for (int ks = 0; ks < 4; ks++) {
            uint32_t k0 = ks * 16;
            uint32_t aoff = (aRow * HPAD + k0 + aKof) * 2;
            uint32_t ahi[4], alo[4];
            LDSM4(ahi, shi + aoff);
            LDSM4(alo, slo + aoff);
            #pragma unroll
            for (int p = 0; p < 4; p++) {
                uint32_t boff = ((p * 16 + bRowL) * HPAD + k0 + bKof) * 2;
                uint32_t bh[4], bl[4];
                LDSM4(bh, whi + boff);
                LDSM4(bl, wlo + boff);
                MMA(acc[2 * p],     ahi, bh[0], bh[1]);
                MMA(acc[2 * p],     ahi, bl[0], bl[1]);
                MMA(acc[2 * p],     alo, bh[0], bh[1]);
                MMA(acc[2 * p + 1], ahi, bh[2], bh[3]);
                MMA(acc[2 * p + 1], ahi, bl[2], bl[3]);
                MMA(acc[2 * p + 1], alo, bh[2], bh[3]);
            }
        }
    }

    // ================= Layers 2..6 =================
    const int erow = rbase + (lane >> 2);

    for (int l = 0; l < 5; l++) {
        __syncthreads();                   // all warps done reading old W
        stageW(whi, wlo, gwE + (4 + l) * 8192, tid, (l == 4) ? 32 : 64);
        // epilogue of prev layer -> H planes (own warp rows only)
        const float* bb = sB + l * 64;
        #pragma unroll
        for (int nt = 0; nt < 8; nt++) {
            int c0 = nt * 8 + (lane & 3) * 2;
            float b0v = bb[c0], b1v = bb[c0 + 1];
            float v0 = fmaxf(acc[nt][0] + b0v, 0.f);
            float v1 = fmaxf(acc[nt][1] + b1v, 0.f);
            float v2 = fmaxf(acc[nt][2] + b0v, 0.f);
            float v3 = fmaxf(acc[nt][3] + b1v, 0.f);
            uint32_t o0 = (uint32_t)(erow * HPAD + c0) * 2;
            uint32_t o1 = (uint32_t)((erow + 8) * HPAD + c0) * 2;
            *(uint32_t*)(smem + SH_HI + o0) = bf2(v0, v1);
            *(uint32_t*)(smem + SH_HI + o1) = bf2(v2, v3);
            *(uint32_t*)(smem + SH_LO + o0) = bf2(bfr(v0), bfr(v1));
            *(uint32_t*)(smem + SH_LO + o1) = bf2(bfr(v2), bfr(v3));
        }
        __syncwarp();
        CP_COMMIT(); CP_WAIT0();
        __syncthreads();                   // new W visible

        if (l < 4) {
            #pragma unroll
            for (int i = 0; i < 8; i++)
                #pragma unroll
                for (int j = 0; j < 4; j++) acc[i][j] = 0.f;
            #pragma unroll
            for (int ks = 0; ks < 4; ks++) {
                uint32_t k0 = ks * 16;
                uint32_t aoff = (aRow * HPAD + k0 + aKof) * 2;
                uint32_t ahi[4], alo[4];
                LDSM4(ahi, shi + aoff);
                LDSM4(alo, slo + aoff);
                #pragma unroll
                for (int p = 0; p < 4; p++) {
                    uint32_t boff = ((p * 16 + bRowL) * HPAD + k0 + bKof) * 2;
                    uint32_t bh[4], bl[4];
                    LDSM4(bh, whi + boff);
                    LDSM4(bl, wlo + boff);
                    MMA(acc[2 * p],     ahi, bh[0], bh[1]);
                    MMA(acc[2 * p],     ahi, bl[0], bl[1]);
                    MMA(acc[2 * p],     alo, bh[0], bh[1]);
                    MMA(acc[2 * p + 1], ahi, bh[2], bh[3]);
                    MMA(acc[2 * p + 1], ahi, bl[2], bl[3]);
                    MMA(acc[2 * p + 1], alo, bh[2], bh[3]);
                }
            }
        }
    }

    // ---- Layer 6 MMA: [64,64] x [64,18] (N padded 32) ----
    float acc6[3][4];
    #pragma unroll
    for (int i = 0; i < 3; i++)
        #pragma unroll
        for (int j = 0; j < 4; j++) acc6[i][j] = 0.f;

    #pragma unroll
    for (int ks = 0; ks < 4; ks++) {
        uint32_t k0 = ks * 16;
        uint32_t aoff = (aRow * HPAD + k0 + aKof) * 2;
        uint32_t ahi[4], alo[4];
        LDSM4(ahi, shi + aoff);
        LDSM4(alo, slo + aoff);
        #pragma unroll
        for (int p = 0; p < 2; p++) {
            uint32_t boff = ((p * 16 + bRowL) * HPAD + k0 + bKof) * 2;
            uint32_t bh[4], bl[4];
            LDSM4(bh, whi + boff);
            LDSM4(bl, wlo + boff);
            MMA(acc6[2 * p],     ahi, bh[0], bh[1]);
            MMA(acc6[2 * p],     ahi, bl[0], bl[1]);
            MMA(acc6[2 * p],     alo, bh[0], bh[1]);
            if (p == 0) {
                MMA(acc6[1], ahi, bh[2], bh[3]);
                MMA(acc6[1], ahi, bl[2], bl[3]);
                MMA(acc6[1], alo, bh[2], bh[3]);
            }
        }
    }

    // output scatter
    const int r0 = erow, r1 = erow + 8;
    int pr0 = (r0 < nrows) ? g_perm[off + tile * ROWS + r0] : -1;
    int pr1 = (r1 < nrows) ? g_perm[off + tile * ROWS + r1] : -1;
    const float* b6b = sB + 320;
    #pragma unroll
    for (int nt = 0; nt < 3; nt++) {
        int c0 = nt * 8 + (lane & 3) * 2;
        if (c0 + 1 < ACT) {
            float b0v = b6b[c0], b1v = b6b[c0 + 1];
            if (pr0 >= 0) {
                out[(size_t)pr0 * ACT + c0]     = acc6[nt][0] + b0v;
                out[(size_t)pr0 * ACT + c0 + 1] = acc6[nt][1] + b1v;
            }
            if (pr1 >= 0) {
                out[(size_t)pr1 * ACT + c0]     = acc6[nt][2] + b0v;
                out[(size_t)pr1 * ACT + c0 + 1] = acc6[nt][3] + b1v;
            }
        }
    }
}

extern "C" void kernel_launch(void* const* d_in, const int* in_sizes, int n_in,
                              void* d_out, int out_size) {
    const float* X  = (const float*)d_in[0];
    const int*   rm = (const int*)d_in[1];
    const float* W1 = (const float*)d_in[2];  const float* b1 = (const float*)d_in[3];
    const float* W2 = (const float*)d_in[4];  const float* b2 = (const float*)d_in[5];
    const float* W3 = (const float*)d_in[6];  const float* b3 = (const float*)d_in[7];
    const float* W4 = (const float*)d_in[8];  const float* b4 = (const float*)d_in[9];
    const float* W5 = (const float*)d_in[10]; const float* b5 = (const float*)d_in[11];
    const float* W6 = (const float*)d_in[12]; const float* b6 = (const float*)d_in[13];
    float* out = (float*)d_out;

    cudaFuncSetAttribute(k_moe, cudaFuncAttributeMaxDynamicSharedMemorySize, SMEM_TOTAL);

    k_zero<<<1, 32>>>();
    k_hist<<<NB / (SORT_THR * 4), SORT_THR>>>((const int4*)rm);
    k_prefix<<<1, 1>>>();
    k_scatter<<<NB / (SORT_THR * 4), SORT_THR>>>((const int4*)rm);
    k_wconv<<<(WCONV_TOTAL + 255) / 256, 256>>>(W1, W2, W3, W4, W5, W6);

    dim3 grid(NB / ROWS, NEXP);
    k_moe<<<grid, NTHR, SMEM_TOTAL>>>(X, b1, b2, b3, b4, b5, b6, out);
}